// round 8
// baseline (speedup 1.0000x reference)
#include <cuda_runtime.h>
#include <math_constants.h>

// PhiCell hysteresis scan: out_i = clamp(out_{i-1}, x_i, x_i + 1), x_i = in_i*k.
// Clamp-map composition is associative -> single-pass scan.
// R8: 256 fat tiles (32768 elems each). Every tile's FULL predecessor set (<=255)
// is read in ONE parallel lookback shot: 8 warps x 32 lanes, one window per warp,
// butterfly tree compose, smem fold. No PRE chaining, no serial window walk.

#define BLOCK 256
#define ITEMS 128
#define CHUNK (BLOCK * ITEMS)   // 32768 elements per tile
#define MAXB  256

#define FLAG_INV 0
#define FLAG_AGG 1

struct CH { float L, H; };

__device__ __forceinline__ CH ch_id() {
    CH r; r.L = -CUDART_INF_F; r.H = CUDART_INF_F; return r;
}
// compose: apply a FIRST, then b
__device__ __forceinline__ CH ch_comp(CH a, CH b) {
    CH r;
    r.L = fminf(fmaxf(a.L, b.L), b.H);
    r.H = fminf(fmaxf(a.H, b.L), b.H);
    return r;
}

// write-once descriptor slots + flag
__device__ float2 g_agg[MAXB];
__device__ int    g_flag[MAXB];

__device__ __forceinline__ void st_flag_release(int i, int f) {
    asm volatile("st.global.release.gpu.b32 [%0], %1;"
                 :: "l"(&g_flag[i]), "r"(f) : "memory");
}
__device__ __forceinline__ int ld_flag_acquire(int i) {
    int f;
    asm volatile("ld.global.acquire.gpu.b32 %0, [%1];"
                 : "=r"(f) : "l"(&g_flag[i]) : "memory");
    return f;
}

__device__ __forceinline__ CH warp_incl_scan(CH v, int lane) {
#pragma unroll
    for (int off = 1; off < 32; off <<= 1) {
        float pl = __shfl_up_sync(0xffffffffu, v.L, off);
        float ph = __shfl_up_sync(0xffffffffu, v.H, off);
        if (lane >= off) { CH p; p.L = pl; p.H = ph; v = ch_comp(p, v); }
    }
    return v;
}

// exclusive composite of all lower-threadIdx threads (identity for t==0)
__device__ CH block_excl_scan(CH v) {
    __shared__ CH ws[BLOCK / 32];
    int lane = threadIdx.x & 31;
    int wid  = threadIdx.x >> 5;

    CH vi = warp_incl_scan(v, lane);
    if (lane == 31) ws[wid] = vi;
    __syncthreads();
    if (wid == 0) {
        CH w = (lane < BLOCK / 32) ? ws[lane] : ch_id();
        w = warp_incl_scan(w, lane);
        if (lane < BLOCK / 32) ws[lane] = w;
    }
    __syncthreads();
    CH wp = (wid > 0) ? ws[wid - 1] : ch_id();

    float pl = __shfl_up_sync(0xffffffffu, vi.L, 1);
    float ph = __shfl_up_sync(0xffffffffu, vi.H, 1);
    CH ve = ch_id();
    if (lane > 0) { ve.L = pl; ve.H = ph; }
    return ch_comp(wp, ve);
}

// reset tile flags before each scan (graph replays reuse g_flag)
__global__ void k_reset(int nb) {
    int i = threadIdx.x;
    if (i < nb) g_flag[i] = FLAG_INV;
}

__global__ void __launch_bounds__(BLOCK)
k_scan(const float* __restrict__ in, const float* __restrict__ kw,
       const float* __restrict__ stt, float* __restrict__ out,
       int n, int out_size) {
    __shared__ CH s_part[BLOCK / 32];
    __shared__ CH s_prefix;

    float k  = __ldg(kw);
    int bid  = blockIdx.x;
    int tid  = threadIdx.x;
    int base = bid * CHUNK + tid * ITEMS;
    const float4* p = reinterpret_cast<const float4*>(in + base);

    // ---- phase A: per-thread composite of its 128 contiguous elements ----
    CH c = ch_id();
#pragma unroll
    for (int q = 0; q < ITEMS / 4; q++) {
        float4 x4 = __ldg(&p[q]);
        float a0 = x4.x * k, a1 = x4.y * k, a2 = x4.z * k, a3 = x4.w * k;
        c.L = fminf(fmaxf(c.L, a0), a0 + 1.0f);
        c.H = fminf(fmaxf(c.H, a0), a0 + 1.0f);
        c.L = fminf(fmaxf(c.L, a1), a1 + 1.0f);
        c.H = fminf(fmaxf(c.H, a1), a1 + 1.0f);
        c.L = fminf(fmaxf(c.L, a2), a2 + 1.0f);
        c.H = fminf(fmaxf(c.H, a2), a2 + 1.0f);
        c.L = fminf(fmaxf(c.L, a3), a3 + 1.0f);
        c.H = fminf(fmaxf(c.H, a3), a3 + 1.0f);
    }

    CH e = block_excl_scan(c);   // contains __syncthreads

    // publish tile aggregate (write-once + release flag)
    if (tid == BLOCK - 1) {
        CH t = ch_comp(e, c);
        g_agg[bid] = make_float2(t.L, t.H);
        st_flag_release(bid, FLAG_AGG);
    }

    // ---- lookback: ALL predecessors in one parallel shot ----
    // warp w, lane l covers predecessor idx = bid-1-(32w+l); id-pad if < 0.
    int w    = tid >> 5;
    int lane = tid & 31;
    CH v = ch_id();
    int idx = bid - 1 - (w * 32 + lane);
    if (idx >= 0) {
        int f;
        do { f = ld_flag_acquire(idx); } while (f == FLAG_INV);
        float2 a = g_agg[idx];
        v.L = a.x; v.H = a.y;
    }
    // butterfly tree: lane receives from lane+off (an EARLIER tile), applies it first
#pragma unroll
    for (int off = 1; off < 32; off <<= 1) {
        float bl = __shfl_down_sync(0xffffffffu, v.L, off);
        float bh = __shfl_down_sync(0xffffffffu, v.H, off);
        if (lane + off < 32) { CH b; b.L = bl; b.H = bh; v = ch_comp(b, v); }
    }
    if (lane == 0) s_part[w] = v;   // window composite (id if window empty)
    __syncthreads();

    if (tid == 0) {
        // fold windows earliest-first: window 7 is the earliest
        CH acc = ch_id();
#pragma unroll
        for (int j = BLOCK / 32 - 1; j >= 0; j--) acc = ch_comp(acc, s_part[j]);
        s_prefix = acc;
    }
    __syncthreads();

    // ---- phase B: re-read input (L2-hot), apply recurrence, write ----
    CH my = ch_comp(s_prefix, e);
    float s0   = __ldg(stt);
    float prev = fminf(fmaxf(s0, my.L), my.H);   // = out[base-1]

    float4* o = reinterpret_cast<float4*>(out + base);
#pragma unroll
    for (int q = 0; q < ITEMS / 4; q++) {
        float4 x4 = __ldg(&p[q]);
        float4 r;
        float a;
        a = x4.x * k; prev = fminf(fmaxf(prev, a), a + 1.0f); r.x = prev;
        a = x4.y * k; prev = fminf(fmaxf(prev, a), a + 1.0f); r.y = prev;
        a = x4.z * k; prev = fminf(fmaxf(prev, a), a + 1.0f); r.z = prev;
        a = x4.w * k; prev = fminf(fmaxf(prev, a), a + 1.0f); r.w = prev;
        __stcs(&o[q], r);
    }

    // new_state appended after T outputs, if present
    if (base + ITEMS == n && out_size > n) out[n] = prev;
}

extern "C" void kernel_launch(void* const* d_in, const int* in_sizes, int n_in,
                              void* d_out, int out_size) {
    const float* in  = (const float*)d_in[0];   // inputs [1, T]
    const float* stt = (const float*)d_in[1];   // state  [1, 1]
    const float* kw  = (const float*)d_in[2];   // kernel [1, 1]
    float* out = (float*)d_out;

    int n  = in_sizes[0];
    int nb = n / CHUNK;                         // 2^23 / 32768 = 256 tiles

    k_reset<<<1, BLOCK>>>(nb);
    k_scan<<<nb, BLOCK>>>(in, kw, stt, out, n, out_size);
}

// round 9
// speedup vs baseline: 1.2551x; 1.2551x over previous
#include <cuda_runtime.h>
#include <math_constants.h>

// PhiCell hysteresis scan: out_i = clamp(out_{i-1}, x_i, x_i + 1), x_i = in_i*k.
// Clamp-map composition is associative -> scan over (L,H) clamp maps.
// R9: two kernels. K1: per-block composites + "last block" scans all 4096
// composites (threadfence-reduction pattern, no spinning). K2: apply + write.

#define BLOCK 256
#define ITEMS 8
#define CHUNK (BLOCK * ITEMS)   // 2048 elements per tile
#define MAXB  4096

struct CH { float L, H; };

__device__ __forceinline__ CH ch_id() {
    CH r; r.L = -CUDART_INF_F; r.H = CUDART_INF_F; return r;
}
// compose: apply a FIRST, then b
__device__ __forceinline__ CH ch_comp(CH a, CH b) {
    CH r;
    r.L = fminf(fmaxf(a.L, b.L), b.H);
    r.H = fminf(fmaxf(a.H, b.L), b.H);
    return r;
}

__device__ float2 g_part[MAXB];
__device__ float2 g_excl[MAXB];
__device__ int    g_cnt;          // zero-init; last block resets -> replay-safe

__device__ __forceinline__ CH warp_incl_scan(CH v, int lane) {
#pragma unroll
    for (int off = 1; off < 32; off <<= 1) {
        float pl = __shfl_up_sync(0xffffffffu, v.L, off);
        float ph = __shfl_up_sync(0xffffffffu, v.H, off);
        if (lane >= off) { CH p; p.L = pl; p.H = ph; v = ch_comp(p, v); }
    }
    return v;
}

// exclusive composite of all lower-threadIdx threads (identity for t==0)
__device__ CH block_excl_scan(CH v) {
    __shared__ CH ws[BLOCK / 32];
    int lane = threadIdx.x & 31;
    int wid  = threadIdx.x >> 5;

    CH vi = warp_incl_scan(v, lane);
    if (lane == 31) ws[wid] = vi;
    __syncthreads();
    if (wid == 0) {
        CH w = (lane < BLOCK / 32) ? ws[lane] : ch_id();
        w = warp_incl_scan(w, lane);
        if (lane < BLOCK / 32) ws[lane] = w;
    }
    __syncthreads();
    CH wp = (wid > 0) ? ws[wid - 1] : ch_id();

    float pl = __shfl_up_sync(0xffffffffu, vi.L, 1);
    float ph = __shfl_up_sync(0xffffffffu, vi.H, 1);
    CH ve = ch_id();
    if (lane > 0) { ve.L = pl; ve.H = ph; }
    return ch_comp(wp, ve);
}

__device__ __forceinline__ void absorb(CH& c, float a) {
    float ap = a + 1.0f;
    c.L = fminf(fmaxf(c.L, a), ap);
    c.H = fminf(fmaxf(c.H, a), ap);
}

// K1: per-block composite; last finishing block scans all composites.
__global__ void __launch_bounds__(BLOCK)
k_phase1(const float* __restrict__ in, const float* __restrict__ kw) {
    __shared__ bool s_last;
    float k = __ldg(kw);
    int bid = blockIdx.x;
    int tid = threadIdx.x;
    const float4* p = reinterpret_cast<const float4*>(in + bid * CHUNK + tid * ITEMS);

    float4 xa = __ldg(&p[0]);
    float4 xb = __ldg(&p[1]);
    CH c = ch_id();
    absorb(c, xa.x * k); absorb(c, xa.y * k);
    absorb(c, xa.z * k); absorb(c, xa.w * k);
    absorb(c, xb.x * k); absorb(c, xb.y * k);
    absorb(c, xb.z * k); absorb(c, xb.w * k);

    CH e = block_excl_scan(c);

    if (tid == BLOCK - 1) {
        CH t = ch_comp(e, c);
        g_part[bid] = make_float2(t.L, t.H);
        __threadfence();
        int old = atomicAdd(&g_cnt, 1);
        s_last = (old == (int)gridDim.x - 1);
    }
    __syncthreads();

    if (s_last) {
        __threadfence();                       // acquire side
        const int P = MAXB / BLOCK;            // 16
        int nb = gridDim.x;
        CH loc[P];
        CH acc = ch_id();
#pragma unroll
        for (int j = 0; j < P; j++) {
            int i = tid * P + j;
            CH x = ch_id();
            if (i < nb) { float2 f = g_part[i]; x.L = f.x; x.H = f.y; }
            acc = ch_comp(acc, x);
            loc[j] = acc;                      // local inclusive
        }
        CH te = block_excl_scan(acc);
#pragma unroll
        for (int j = 0; j < P; j++) {
            int i = tid * P + j;
            if (i < nb) {
                CH ex = (j == 0) ? te : ch_comp(te, loc[j - 1]);
                g_excl[i] = make_float2(ex.L, ex.H);
            }
        }
        if (tid == 0) g_cnt = 0;               // reset for next graph replay
    }
}

// K2: recompute local prefix, apply global prefix, write outputs.
__global__ void __launch_bounds__(BLOCK)
k_phase2(const float* __restrict__ in, const float* __restrict__ kw,
         const float* __restrict__ stt, float* __restrict__ out,
         int n, int out_size) {
    float k  = __ldg(kw);
    int bid  = blockIdx.x;
    int tid  = threadIdx.x;
    int base = bid * CHUNK + tid * ITEMS;
    const float4* p = reinterpret_cast<const float4*>(in + base);

    float4 xa = __ldg(&p[0]);
    float4 xb = __ldg(&p[1]);
    float x0 = xa.x * k, x1 = xa.y * k, x2 = xa.z * k, x3 = xa.w * k;
    float x4 = xb.x * k, x5 = xb.y * k, x6 = xb.z * k, x7 = xb.w * k;

    CH c = ch_id();
    absorb(c, x0); absorb(c, x1); absorb(c, x2); absorb(c, x3);
    absorb(c, x4); absorb(c, x5); absorb(c, x6); absorb(c, x7);

    CH e = block_excl_scan(c);

    float2 be2 = g_excl[bid];
    CH be; be.L = be2.x; be.H = be2.y;
    CH my = ch_comp(be, e);

    float s0   = __ldg(stt);
    float prev = fminf(fmaxf(s0, my.L), my.H);   // = out[base-1]

    float4 r;
    prev = fminf(fmaxf(prev, x0), x0 + 1.0f); r.x = prev;
    prev = fminf(fmaxf(prev, x1), x1 + 1.0f); r.y = prev;
    prev = fminf(fmaxf(prev, x2), x2 + 1.0f); r.z = prev;
    prev = fminf(fmaxf(prev, x3), x3 + 1.0f); r.w = prev;
    float4* o = reinterpret_cast<float4*>(out + base);
    __stcs(&o[0], r);
    prev = fminf(fmaxf(prev, x4), x4 + 1.0f); r.x = prev;
    prev = fminf(fmaxf(prev, x5), x5 + 1.0f); r.y = prev;
    prev = fminf(fmaxf(prev, x6), x6 + 1.0f); r.z = prev;
    prev = fminf(fmaxf(prev, x7), x7 + 1.0f); r.w = prev;
    __stcs(&o[1], r);

    // new_state appended after T outputs, if present
    if (base + ITEMS == n && out_size > n) out[n] = prev;
}

extern "C" void kernel_launch(void* const* d_in, const int* in_sizes, int n_in,
                              void* d_out, int out_size) {
    const float* in  = (const float*)d_in[0];   // inputs [1, T]
    const float* stt = (const float*)d_in[1];   // state  [1, 1]
    const float* kw  = (const float*)d_in[2];   // kernel [1, 1]
    float* out = (float*)d_out;

    int n  = in_sizes[0];
    int nb = n / CHUNK;                         // 2^23 / 2048 = 4096 tiles

    k_phase1<<<nb, BLOCK>>>(in, kw);
    k_phase2<<<nb, BLOCK>>>(in, kw, stt, out, n, out_size);
}